// round 5
// baseline (speedup 1.0000x reference)
#include <cuda_runtime.h>
#include <cuda_fp16.h>
#include <stdint.h>
#include <string.h>

// Problem constants
#define IN_F   2048
#define OUTF   512
#define NB     8
#define BATCH  16

// Packed bits: g_pkw[fb16][out][sub] : uint32. Bit pair (2j, 2j+1) holds the
// weight bits for f = fb16*16 + j, columns (out*8 + sub) and (out*8 + sub + 4).
// Independent of batch index b. Dims: 128 x 512 x 4 = 262144 words = 1 MB.
__device__ uint32_t g_pkw[128 * 512 * 4];

static __device__ __forceinline__ __half2 u2h2(uint32_t u) {
    __half2 h; memcpy(&h, &u, 4); return h;
}
static __device__ __forceinline__ uint32_t h22u(__half2 h) {
    uint32_t u; memcpy(&u, &h, 4); return u;
}

// ---------------------------------------------------------------------------
// Pack kernel: binarize weight (>= 0.5). Thread (out, sub) packs columns
// out*8+sub (bit 2j) and out*8+sub+4 (bit 2j+1) for 16 consecutive f.
// idx = fb16*2048 + out*4 + sub.
// ---------------------------------------------------------------------------
__global__ void pack_kernel(const float* __restrict__ w) {
    int idx = blockIdx.x * blockDim.x + threadIdx.x;
    int fb16 = idx >> 11;          // f-chunk of 16
    int rem  = idx & 2047;         // out*4 + sub
    int outc = (rem >> 2) * 8 + (rem & 3);
    uint32_t word = 0;
#pragma unroll
    for (int j = 0; j < 16; j++) {
        size_t rowoff = (size_t)(fb16 * 16 + j) * 4096;
        float v0 = __ldg(w + rowoff + outc);
        float v1 = __ldg(w + rowoff + outc + 4);
        word |= ((v0 >= 0.5f ? 1u : 0u) | (v1 >= 0.5f ? 2u : 0u)) << (2 * j);
    }
    g_pkw[idx] = word;
}

// ---------------------------------------------------------------------------
// Scan kernel: each thread advances TWO rows, (b0, out) and (b0+8, out),
// owning lanes {sub, sub+4} of each as one half2 per row. The two rows share
// the same weight mask (mask is b-independent), so mask prep is amortized.
// CSA step in 6 fp16 fma-class ops (exact algebraic identities):
//   r  = xor(s,a)  = fma(a, 1-2s, s)
//   mj = maj(s,a,c)= fma(c, r, s*a)
//   s' = xor(r,c)  = fma(c, 1-2r, r)
// Carry shift: previous thread's mj is exactly the needed pair; one shfl per
// row (wraparound src for sub 0, then <<16 to zero the lane-0 carry-in).
// Grid: 128 blocks x 128 threads -> 512 warps, 1 warp/SMSP on 128 SMs; the
// two independent 34-cycle carry chains per warp interleave to hide latency.
// Output float32: s at out[b*4096 + o*8 + lane], c at +65536 floats.
// ---------------------------------------------------------------------------
__global__ void __launch_bounds__(128, 1)
scan_kernel(const float* __restrict__ x, float* __restrict__ out) {
    __shared__ uint32_t sxa[IN_F];  // x row b0   as duplicated half2
    __shared__ uint32_t sxb[IN_F];  // x row b0+8 as duplicated half2
    __shared__ uint32_t slut[4];    // 2-bit pattern -> half2 lane mask

    const int tid = threadIdx.x;
    const int blk = blockIdx.x;
    const int b0 = blk >> 4;                 // 0..7 ; pair row is b0+8
    const int out_base = (blk & 15) << 5;    // 32 outs per block

    const float* xra = x + b0 * IN_F;
    const float* xrb = x + (b0 + 8) * IN_F;
#pragma unroll
    for (int i = 0; i < IN_F / 128; i++) {
        int k = tid + i * 128;
        sxa[k] = h22u(__half2half2(__float2half(xra[k])));
        sxb[k] = h22u(__half2half2(__float2half(xrb[k])));
    }
    if (tid < 4)
        slut[tid] = ((tid & 1) ? 0x0000FFFFu : 0u) | ((tid & 2) ? 0xFFFF0000u : 0u);
    __syncthreads();

    const int sub  = tid & 3;
    const int lane = tid & 31;
    const int srcl = (sub == 0) ? lane + 3 : lane - 1;   // carry source lane
    const uint32_t shamt = (sub == 0) ? 16u : 0u;        // zero global lane 0
    // pk index: (out_base + out_local)*4 + sub = out_base*4 + tid
    const uint32_t* pk = g_pkw + out_base * 4 + tid;     // + fb16*2048 per chunk
    const __half2 neg2 = __float2half2_rn(-2.0f);
    const __half2 one  = __float2half2_rn(1.0f);

    uint32_t w = __ldg(pk);

    // f = 0 initializes state: s = a(0), c = 0.
    {
        uint32_t m0 = slut[w & 3u];
        // handled below via peel
    }
    uint32_t minit = slut[w & 3u];
    __half2 sA = u2h2(sxa[0] & minit);
    __half2 sB = u2h2(sxb[0] & minit);
    __half2 cA = __float2half2_rn(0.0f);
    __half2 cB = __float2half2_rn(0.0f);

    auto step2 = [&](uint32_t m, uint32_t xua, uint32_t xub) {
        __half2 aA = u2h2(xua & m);
        __half2 aB = u2h2(xub & m);
        // row A
        __half2 m1A = __hmul2(sA, aA);
        __half2 g1A = __hfma2(sA, neg2, one);
        __half2 rA  = __hfma2(aA, g1A, sA);
        __half2 mjA = __hfma2(cA, rA, m1A);
        __half2 g2A = __hfma2(rA, neg2, one);
        sA = __hfma2(cA, g2A, rA);
        // row B
        __half2 m1B = __hmul2(sB, aB);
        __half2 g1B = __hfma2(sB, neg2, one);
        __half2 rB  = __hfma2(aB, g1B, sB);
        __half2 mjB = __hfma2(cB, rB, m1B);
        __half2 g2B = __hfma2(rB, neg2, one);
        sB = __hfma2(cB, g2B, rB);
        // carry shifts
        uint32_t pA = __shfl_sync(0xFFFFFFFFu, h22u(mjA), srcl);
        uint32_t pB = __shfl_sync(0xFFFFFFFFu, h22u(mjB), srcl);
        cA = u2h2(pA << shamt);
        cB = u2h2(pB << shamt);
    };

    uint32_t wn = __ldg(pk + 2048);
#pragma unroll
    for (int j = 1; j < 16; j++)
        step2(slut[(w >> (2 * j)) & 3u], sxa[j], sxb[j]);
    w = wn;

#pragma unroll 1
    for (int fb16 = 1; fb16 < 128; fb16++) {
        uint32_t wnext = 0;
        if (fb16 < 127) wnext = __ldg(pk + (fb16 + 1) * 2048);
        const uint32_t* sap = sxa + fb16 * 16;
        const uint32_t* sbp = sxb + fb16 * 16;
#pragma unroll
        for (int j = 0; j < 16; j++)
            step2(slut[(w >> (2 * j)) & 3u], sap[j], sbp[j]);
        w = wnext;
    }

    // Output as float32. Thread sub holds lanes (sub, sub+4) of both rows.
    const int out_i = out_base + (tid >> 2);
    const int baseA = b0 * 4096 + out_i * 8;
    const int baseB = (b0 + 8) * 4096 + out_i * 8;
    float2 sAf = __half22float2(sA), cAf = __half22float2(cA);
    float2 sBf = __half22float2(sB), cBf = __half22float2(cB);
    out[baseA + sub]             = sAf.x;
    out[baseA + sub + 4]         = sAf.y;
    out[65536 + baseA + sub]     = cAf.x;
    out[65536 + baseA + sub + 4] = cAf.y;
    out[baseB + sub]             = sBf.x;
    out[baseB + sub + 4]         = sBf.y;
    out[65536 + baseB + sub]     = cBf.x;
    out[65536 + baseB + sub + 4] = cBf.y;
}

// ---------------------------------------------------------------------------
extern "C" void kernel_launch(void* const* d_in, const int* in_sizes, int n_in,
                              void* d_out, int out_size) {
    const float* x  = (const float*)d_in[0];   // (16, 2048) fp32
    const float* wt = (const float*)d_in[1];   // (2048, 4096) fp32
    float* out = (float*)d_out;                // 131072 fp32: [s | c]

    pack_kernel<<<1024, 256>>>(wt);
    scan_kernel<<<128, 128>>>(x, out);
}

// round 6
// speedup vs baseline: 1.4858x; 1.4858x over previous
#include <cuda_runtime.h>
#include <cuda_fp16.h>
#include <stdint.h>
#include <string.h>

// Problem constants
#define IN_F   2048
#define OUTF   512
#define NB     8
#define BATCH  16

// Packed bits: g_pkw[fb32][out*8+lane] : uint32. Bit j holds the binarized
// weight for f = fb32*32 + j, column out*8+lane. Independent of batch.
// Dims: 64 x 4096 = 262144 words = 1 MB.
__device__ uint32_t g_pkw[64 * 4096];

static __device__ __forceinline__ __half2 u2h2(uint32_t u) {
    __half2 h; memcpy(&h, &u, 4); return h;
}
static __device__ __forceinline__ uint32_t h22u(__half2 h) {
    uint32_t u; memcpy(&u, &h, 4); return u;
}

// ---------------------------------------------------------------------------
// Pack kernel: binarize weight (>= 0.5), 1 bit per f, 32 f per word.
// idx = fb32*4096 + col. Adjacent threads read adjacent columns -> coalesced.
// ---------------------------------------------------------------------------
__global__ void pack_kernel(const float* __restrict__ w) {
    int idx = blockIdx.x * blockDim.x + threadIdx.x;
    int fb32 = idx >> 12;
    int col  = idx & 4095;
    uint32_t word = 0;
#pragma unroll
    for (int j = 0; j < 32; j++) {
        float v = __ldg(w + (size_t)(fb32 * 32 + j) * 4096 + col);
        word |= (v >= 0.5f ? 1u : 0u) << j;
    }
    g_pkw[idx] = word;
}

// ---------------------------------------------------------------------------
// Scan kernel. half2 state packs rows {b0, b0+8} for ONE lane k; 8 threads
// per row-pair (lanes 0..7). Both half2 lanes share the same weight bit, so
// the mask is a 2-shift sign-extend from the packed word (no LUT, no LDS on
// the a-path). x pairs are preloaded to smem and fetched as broadcast
// LDS.128 once per 4 steps.
// CSA step: 6 fp16 fma-class ops (identical per-lane sequence to R4):
//   m1=s*a; g1=fma(s,-2,1); r=fma(a,g1,s); mj=fma(c,r,m1);
//   g2=fma(r,-2,1); s'=fma(c,g2,r)
// Carry: c[k] = mj[k-1]; one shfl per warp-step (serves both rows) + AND to
// zero lane 0's carry-in.
// Grid: 128 blocks x 256 threads = 1024 warps = 2 warps/SMSP on 128 SMs.
// ---------------------------------------------------------------------------
__global__ void __launch_bounds__(256, 1)
scan_kernel(const float* __restrict__ x, float* __restrict__ out) {
    __shared__ uint32_t sx[IN_F];   // {half(x[b0,f]), half(x[b0+8,f])}

    const int tid = threadIdx.x;
    const int blk = blockIdx.x;
    const int b0 = blk >> 4;                 // 0..7 ; pair row is b0+8
    const int out_base = (blk & 15) << 5;    // 32 outs per block

    const float* xa = x + b0 * IN_F;
    const float* xb = x + (b0 + 8) * IN_F;
#pragma unroll
    for (int i = 0; i < IN_F / 256; i++) {
        int k = tid + i * 256;
        __half ha = __float2half(xa[k]);     // matches jnp astype(float16)
        __half hb = __float2half(xb[k]);
        sx[k] = h22u(__halves2half2(ha, hb));
    }
    __syncthreads();

    const int sub  = tid & 7;                // lane k within row-pair
    const int lane = tid & 31;
    const int srcl = sub ? (lane - 1) : lane;       // carry source lane
    const uint32_t zmask = sub ? 0xFFFFFFFFu : 0u;  // zero lane-0 carry-in
    const uint32_t* pk = g_pkw + out_base * 8 + tid;   // + fb32*4096 per chunk
    const __half2 neg2 = __float2half2_rn(-2.0f);
    const __half2 one  = __float2half2_rn(1.0f);

    uint32_t w = __ldg(pk);

    // f = 0 initializes the state: s = a(0), c = 0.
    uint32_t m0 = (uint32_t)(((int32_t)(w << 31)) >> 31);
    __half2 s = u2h2(sx[0] & m0);
    __half2 c = __float2half2_rn(0.0f);

    auto step = [&](uint32_t wv, int j, uint32_t xu) {
        uint32_t m = (uint32_t)(((int32_t)(wv << (31 - j))) >> 31);
        __half2 a  = u2h2(xu & m);
        __half2 m1 = __hmul2(s, a);
        __half2 g1 = __hfma2(s, neg2, one);
        __half2 r  = __hfma2(a, g1, s);      // xor(s, a)
        __half2 mj = __hfma2(c, r, m1);      // maj(s, a, c)
        __half2 g2 = __hfma2(r, neg2, one);
        s = __hfma2(c, g2, r);               // xor(r, c)
        uint32_t prev = __shfl_sync(0xFFFFFFFFu, h22u(mj), srcl);
        c = u2h2(prev & zmask);
    };

    const uint4* sx4 = reinterpret_cast<const uint4*>(sx);

    // Chunk 0 (f = 1..31), prefetch next word.
    uint32_t wn = __ldg(pk + 4096);
#pragma unroll
    for (int jj = 0; jj < 8; jj++) {
        uint4 q = sx4[jj];
        if (jj > 0) step(w, 4 * jj + 0, q.x);
        step(w, 4 * jj + 1, q.y);
        step(w, 4 * jj + 2, q.z);
        step(w, 4 * jj + 3, q.w);
    }
    w = wn;

#pragma unroll 1
    for (int fb32 = 1; fb32 < 64; fb32++) {
        uint32_t wnext = 0;
        if (fb32 < 63) wnext = __ldg(pk + (fb32 + 1) * 4096);
        const uint4* p = sx4 + fb32 * 8;
#pragma unroll
        for (int jj = 0; jj < 8; jj++) {
            uint4 q = p[jj];
            step(w, 4 * jj + 0, q.x);
            step(w, 4 * jj + 1, q.y);
            step(w, 4 * jj + 2, q.z);
            step(w, 4 * jj + 3, q.w);
        }
        w = wnext;
    }

    // Output float32. Fully coalesced: block's threads cover 256 consecutive
    // (out,lane) slots. s at out[b*4096 + o*8 + k], c at +65536 floats.
    const int obase = b0 * 4096 + out_base * 8 + tid;
    float2 sf = __half22float2(s);   // .x = row b0, .y = row b0+8
    float2 cf = __half22float2(c);
    out[obase]                 = sf.x;
    out[obase + 32768]         = sf.y;
    out[65536 + obase]         = cf.x;
    out[65536 + obase + 32768] = cf.y;
}

// ---------------------------------------------------------------------------
extern "C" void kernel_launch(void* const* d_in, const int* in_sizes, int n_in,
                              void* d_out, int out_size) {
    const float* x  = (const float*)d_in[0];   // (16, 2048) fp32
    const float* wt = (const float*)d_in[1];   // (2048, 4096) fp32
    float* out = (float*)d_out;                // 131072 fp32: [s | c]

    pack_kernel<<<1024, 256>>>(wt);
    scan_kernel<<<128, 256>>>(x, out);
}

// round 7
// speedup vs baseline: 1.7822x; 1.1994x over previous
#include <cuda_runtime.h>
#include <cuda_fp16.h>
#include <stdint.h>
#include <string.h>

// Problem constants
#define IN_F   2048
#define OUTF   512
#define NB     8
#define BATCH  16

// Packed bits: g_pkw[fb16][out*4+sub] : uint32. Bit pair (2j, 2j+1) holds the
// binarized weights for f = fb16*16 + j, columns out*8 + 2*sub + {0,1}.
// Independent of batch. Dims: 128 x 2048 = 262144 words = 1 MB.
__device__ uint32_t g_pkw[128 * 2048];

static __device__ __forceinline__ __half2 u2h2(uint32_t u) {
    __half2 h; memcpy(&h, &u, 4); return h;
}
static __device__ __forceinline__ uint32_t h22u(__half2 h) {
    uint32_t u; memcpy(&u, &h, 4); return u;
}

// ---------------------------------------------------------------------------
// Pack kernel (R4 layout): binarize weight (>= 0.5), 2 bits per f (adjacent
// columns), 16 f per word. idx = fb16*2048 + (out*4 + sub); columns rem*2,
// rem*2+1. Consecutive threads read consecutive float2 -> coalesced.
// ---------------------------------------------------------------------------
__global__ void pack_kernel(const float* __restrict__ w) {
    int idx = blockIdx.x * blockDim.x + threadIdx.x;
    int fb16 = idx >> 11;         // f-chunk of 16
    int rem  = idx & 2047;        // out*4 + sub -> column base = rem*2
    const float2* wp = reinterpret_cast<const float2*>(w) + rem;
    uint32_t word = 0;
#pragma unroll
    for (int j = 0; j < 16; j++) {
        float2 v = __ldg(wp + (size_t)(fb16 * 16 + j) * 2048);
        word |= ((v.x >= 0.5f ? 1u : 0u) | (v.y >= 0.5f ? 2u : 0u)) << (2 * j);
    }
    g_pkw[idx] = word;
}

// ---------------------------------------------------------------------------
// Scan kernel. Thread sub in {0..3} owns lanes {2sub, 2sub+1} of row-pair
// (b0, b0+8): two half2 states (A = lane 2sub, B = lane 2sub+1), each packing
// the two batch rows. CSA step per half2: 6 fp16 fma-class ops, per-lane
// sequence identical to R4/R6:
//   m1=s*a; g1=fma(s,-2,1); r=fma(a,g1,s); mj=fma(c,r,m1);
//   g2=fma(r,-2,1); s'=fma(c,g2,r)
// Carry ripple: cB' = mjA (LOCAL register rename); only cA' = neighbor's mjB
// crosses threads (1 shfl/step) and sits on the critical cycle only every
// OTHER step -> chain ~20 cyc/step, below the fma-pipe floor (~24).
// B-chain is emitted first so the shfl issues early in each step.
// Grid: 128 blocks x 128 threads = 512 warps = 1 warp/SMSP on 128 SMs.
// ---------------------------------------------------------------------------
__global__ void __launch_bounds__(128, 1)
scan_kernel(const float* __restrict__ x, float* __restrict__ out) {
    __shared__ uint32_t sx[IN_F];   // {half(x[b0,f]), half(x[b0+8,f])}

    const int tid = threadIdx.x;
    const int blk = blockIdx.x;
    const int b0 = blk >> 4;                 // 0..7 ; pair row is b0+8
    const int out_base = (blk & 15) << 5;    // 32 outs per block

    const float* xa = x + b0 * IN_F;
    const float* xb = x + (b0 + 8) * IN_F;
#pragma unroll
    for (int i = 0; i < IN_F / 128; i++) {
        int k = tid + i * 128;
        sx[k] = h22u(__halves2half2(__float2half(xa[k]), __float2half(xb[k])));
    }
    __syncthreads();

    const int sub  = tid & 3;
    const int lane = tid & 31;
    const int srcl = sub ? (lane - 1) : lane;       // carry source lane
    const uint32_t zmask = sub ? 0xFFFFFFFFu : 0u;  // zero lane-0 carry-in
    const uint32_t* pk = g_pkw + out_base * 4 + tid;   // + fb16*2048 per chunk
    const __half2 neg2 = __float2half2_rn(-2.0f);
    const __half2 one  = __float2half2_rn(1.0f);

    uint32_t w = __ldg(pk);

    // f = 0 initializes the state: s = a(0), c = 0.
    uint32_t xv0 = sx[0];
    __half2 sA = u2h2(xv0 & (uint32_t)(((int32_t)(w << 31)) >> 31));
    __half2 sB = u2h2(xv0 & (uint32_t)(((int32_t)(w << 30)) >> 31));
    __half2 cA = __float2half2_rn(0.0f);
    __half2 cB = __float2half2_rn(0.0f);

    auto step = [&](uint32_t wv, int j, uint32_t xu) {
        uint32_t mA = (uint32_t)(((int32_t)(wv << (31 - 2 * j))) >> 31);
        uint32_t mB = (uint32_t)(((int32_t)(wv << (30 - 2 * j))) >> 31);
        __half2 aB = u2h2(xu & mB);
        // B chain first: mjB feeds the shfl -> issue it as early as possible.
        __half2 m1B = __hmul2(sB, aB);
        __half2 g1B = __hfma2(sB, neg2, one);
        __half2 rB  = __hfma2(aB, g1B, sB);
        __half2 mjB = __hfma2(cB, rB, m1B);
        uint32_t prev = __shfl_sync(0xFFFFFFFFu, h22u(mjB), srcl);
        __half2 g2B = __hfma2(rB, neg2, one);
        sB = __hfma2(cB, g2B, rB);
        // A chain (consumes last step's shfl via cA).
        __half2 aA = u2h2(xu & mA);
        __half2 m1A = __hmul2(sA, aA);
        __half2 g1A = __hfma2(sA, neg2, one);
        __half2 rA  = __hfma2(aA, g1A, sA);
        __half2 mjA = __hfma2(cA, rA, m1A);
        __half2 g2A = __hfma2(rA, neg2, one);
        sA = __hfma2(cA, g2A, rA);
        // Carries for next step.
        cB = mjA;                        // local ripple (register rename)
        cA = u2h2(prev & zmask);         // cross-thread, 2-step slack
    };

    const uint4* sx4 = reinterpret_cast<const uint4*>(sx);

    // Chunk 0 (f = 1..15), prefetch next word; x quads loaded at chunk top.
    uint32_t wn = __ldg(pk + 2048);
    {
        uint4 q0 = sx4[0], q1 = sx4[1], q2 = sx4[2], q3 = sx4[3];
        step(w, 1, q0.y);  step(w, 2, q0.z);  step(w, 3, q0.w);
        step(w, 4, q1.x);  step(w, 5, q1.y);  step(w, 6, q1.z);  step(w, 7, q1.w);
        step(w, 8, q2.x);  step(w, 9, q2.y);  step(w, 10, q2.z); step(w, 11, q2.w);
        step(w, 12, q3.x); step(w, 13, q3.y); step(w, 14, q3.z); step(w, 15, q3.w);
    }
    w = wn;

#pragma unroll 1
    for (int fb16 = 1; fb16 < 128; fb16++) {
        uint32_t wnext = 0;
        if (fb16 < 127) wnext = __ldg(pk + (fb16 + 1) * 2048);
        const uint4* p = sx4 + fb16 * 4;
        uint4 q0 = p[0], q1 = p[1], q2 = p[2], q3 = p[3];
        step(w, 0, q0.x);  step(w, 1, q0.y);  step(w, 2, q0.z);  step(w, 3, q0.w);
        step(w, 4, q1.x);  step(w, 5, q1.y);  step(w, 6, q1.z);  step(w, 7, q1.w);
        step(w, 8, q2.x);  step(w, 9, q2.y);  step(w, 10, q2.z); step(w, 11, q2.w);
        step(w, 12, q3.x); step(w, 13, q3.y); step(w, 14, q3.z); step(w, 15, q3.w);
        w = wnext;
    }

    // Output float32. Thread sub holds lanes (2sub, 2sub+1) of rows b0, b0+8.
    // s at out[b*4096 + o*8 + lane], c at +65536 floats.
    const int out_i = out_base + (tid >> 2);
    const int baseA = b0 * 4096 + out_i * 8 + 2 * sub;        // row b0
    const int baseB = baseA + 8 * 4096;                       // row b0+8
    float2 sAf = __half22float2(sA), cAf = __half22float2(cA);
    float2 sBf = __half22float2(sB), cBf = __half22float2(cB);
    out[baseA]             = sAf.x;   // row b0,   lane 2sub
    out[baseA + 1]         = sBf.x;   // row b0,   lane 2sub+1
    out[baseB]             = sAf.y;   // row b0+8, lane 2sub
    out[baseB + 1]         = sBf.y;
    out[65536 + baseA]     = cAf.x;
    out[65536 + baseA + 1] = cBf.x;
    out[65536 + baseB]     = cAf.y;
    out[65536 + baseB + 1] = cBf.y;
}

// ---------------------------------------------------------------------------
extern "C" void kernel_launch(void* const* d_in, const int* in_sizes, int n_in,
                              void* d_out, int out_size) {
    const float* x  = (const float*)d_in[0];   // (16, 2048) fp32
    const float* wt = (const float*)d_in[1];   // (2048, 4096) fp32
    float* out = (float*)d_out;                // 131072 fp32: [s | c]

    pack_kernel<<<1024, 256>>>(wt);
    scan_kernel<<<128, 128>>>(x, out);
}

// round 8
// speedup vs baseline: 1.8543x; 1.0405x over previous
#include <cuda_runtime.h>
#include <cuda_fp16.h>
#include <stdint.h>
#include <string.h>

// Problem constants
#define IN_F   2048
#define OUTF   512
#define NB     8
#define BATCH  16

// Packed bits: g_pkw[fb16][out*4+sub] : uint32. Bit pair (2j, 2j+1) holds the
// binarized weights for f = fb16*16 + j, columns out*8 + 2*sub + {0,1}.
// Independent of batch. Dims: 128 x 2048 = 262144 words = 1 MB.
__device__ uint32_t g_pkw[128 * 2048];

static __device__ __forceinline__ __half2 u2h2(uint32_t u) {
    __half2 h; memcpy(&h, &u, 4); return h;
}
static __device__ __forceinline__ uint32_t h22u(__half2 h) {
    uint32_t u; memcpy(&u, &h, 4); return u;
}

// ---------------------------------------------------------------------------
// Pack kernel: binarize weight (>= 0.5), 2 bits per f (adjacent columns),
// 16 f per word. idx = fb16*2048 + (out*4 + sub); columns rem*2, rem*2+1.
// ---------------------------------------------------------------------------
__global__ void pack_kernel(const float* __restrict__ w) {
    int idx = blockIdx.x * blockDim.x + threadIdx.x;
    int fb16 = idx >> 11;         // f-chunk of 16
    int rem  = idx & 2047;        // out*4 + sub -> column base = rem*2
    const float2* wp = reinterpret_cast<const float2*>(w) + rem;
    uint32_t word = 0;
#pragma unroll
    for (int j = 0; j < 16; j++) {
        float2 v = __ldg(wp + (size_t)(fb16 * 16 + j) * 2048);
        word |= ((v.x >= 0.5f ? 1u : 0u) | (v.y >= 0.5f ? 2u : 0u)) << (2 * j);
    }
    g_pkw[idx] = word;
}

// ---------------------------------------------------------------------------
// Scan kernel. Thread sub in {0..3} owns lanes {2sub, 2sub+1} of row-pair
// (b0, b0+8): half2 state A = lane 2sub, B = lane 2sub+1 (each packs the two
// batch rows). CSA step per half2: 6 fp16 fma ops (same per-lane sequence as
// R4/R6/R7).
// SKEWED PIPELINE: iteration i runs A-step(f=i-1) then B-step(f=i).
//   cB(i)   = mjA(i-1)            -- same-iteration register (4-cyc dep)
//   cA(i-1) = nbr mjB(i-2) via a shfl issued 2 iterations earlier (p2)
// so the shfl latency is covered by ~2 iterations of independent issue.
// Both chains start from (s=0,c=0): a step from (0,0) yields exactly
// (s=a, c=0), so f=0 needs no special init and f=-1 (a=0) is an identity.
// Grid: 128 blocks x 128 threads = 512 warps = 1 warp/SMSP on 128 SMs.
// ---------------------------------------------------------------------------
__global__ void __launch_bounds__(128, 1)
scan_kernel(const float* __restrict__ x, float* __restrict__ out) {
    __shared__ uint32_t sx[IN_F];   // {half(x[b0,f]), half(x[b0+8,f])}

    const int tid = threadIdx.x;
    const int blk = blockIdx.x;
    const int b0 = blk >> 4;                 // 0..7 ; pair row is b0+8
    const int out_base = (blk & 15) << 5;    // 32 outs per block

    const float* xa = x + b0 * IN_F;
    const float* xb = x + (b0 + 8) * IN_F;
#pragma unroll
    for (int i = 0; i < IN_F / 128; i++) {
        int k = tid + i * 128;
        sx[k] = h22u(__halves2half2(__float2half(xa[k]), __float2half(xb[k])));
    }
    __syncthreads();

    const int sub  = tid & 3;
    const int lane = tid & 31;
    const int srcl = sub ? (lane - 1) : lane;       // carry source lane
    const uint32_t zmask = sub ? 0xFFFFFFFFu : 0u;  // lane-0 carry-in is 0
    const uint32_t* pk = g_pkw + out_base * 4 + tid;   // + fb16*2048 per chunk
    const __half2 neg2 = __float2half2_rn(-2.0f);
    const __half2 one  = __float2half2_rn(1.0f);
    const __half2 zero = __float2half2_rn(0.0f);

    // sign-extend bit `b` of v to a full mask
    auto sext = [](uint32_t v, int b) {
        return (uint32_t)(((int32_t)(v << (31 - b))) >> 31);
    };

    __half2 sA = zero, sB = zero;
    __half2 mjA_last = zero;            // mjA(i-1), feeds cB same iteration
    uint32_t p1 = 0, p2 = 0;            // shfl pipeline: p2 is 2 iters old

    // One pipelined iteration: A-step(f-1) then B-step(f).
    auto stepAB = [&](uint32_t mAu, uint32_t xuA, uint32_t mBu, uint32_t xuB) {
        // ---- A-step (f = i-1); cA = 2-iteration-old neighbor mjB ----
        __half2 aA  = u2h2(xuA & mAu);
        __half2 cAv = u2h2(p2 & zmask);
        __half2 m1A = __hmul2(sA, aA);
        __half2 g1A = __hfma2(sA, neg2, one);
        __half2 rA  = __hfma2(aA, g1A, sA);
        __half2 mjA = __hfma2(cAv, rA, m1A);
        __half2 g2A = __hfma2(rA, neg2, one);
        sA = __hfma2(cAv, g2A, rA);
        // ---- B-step (f = i); cB = mjA from THIS iteration ----
        __half2 aB  = u2h2(xuB & mBu);
        __half2 m1B = __hmul2(sB, aB);
        __half2 g1B = __hfma2(sB, neg2, one);
        __half2 rB  = __hfma2(aB, g1B, sB);
        __half2 mjB = __hfma2(mjA, rB, m1B);
        __half2 g2B = __hfma2(rB, neg2, one);
        sB = __hfma2(mjA, g2B, rB);
        mjA_last = mjA;
        // ---- carry exchange, consumed 2 iterations later ----
        p2 = p1;
        p1 = __shfl_sync(0xFFFFFFFFu, h22u(mjB), srcl);
    };

    const uint4* sx4 = reinterpret_cast<const uint4*>(sx);

    uint32_t w = __ldg(pk);
    uint32_t wprev = 0;                 // bits for f<0 read as 0 (identity)
    uint32_t xu_lag = 0;

#pragma unroll 1
    for (int fb16 = 0; fb16 < 128; fb16++) {
        uint32_t wnext = 0;
        if (fb16 < 127) wnext = __ldg(pk + (fb16 + 1) * 2048);
        const uint4* p = sx4 + fb16 * 4;
        uint4 q0 = p[0], q1 = p[1], q2 = p[2], q3 = p[3];
        stepAB(sext(wprev, 30), xu_lag, sext(w, 1),  q0.x);
        stepAB(sext(w, 0),  q0.x, sext(w, 3),  q0.y);
        stepAB(sext(w, 2),  q0.y, sext(w, 5),  q0.z);
        stepAB(sext(w, 4),  q0.z, sext(w, 7),  q0.w);
        stepAB(sext(w, 6),  q0.w, sext(w, 9),  q1.x);
        stepAB(sext(w, 8),  q1.x, sext(w, 11), q1.y);
        stepAB(sext(w, 10), q1.y, sext(w, 13), q1.z);
        stepAB(sext(w, 12), q1.z, sext(w, 15), q1.w);
        stepAB(sext(w, 14), q1.w, sext(w, 17), q2.x);
        stepAB(sext(w, 16), q2.x, sext(w, 19), q2.y);
        stepAB(sext(w, 18), q2.y, sext(w, 21), q2.z);
        stepAB(sext(w, 20), q2.z, sext(w, 23), q2.w);
        stepAB(sext(w, 22), q2.w, sext(w, 25), q3.x);
        stepAB(sext(w, 24), q3.x, sext(w, 27), q3.y);
        stepAB(sext(w, 26), q3.y, sext(w, 29), q3.z);
        stepAB(sext(w, 28), q3.z, sext(w, 31), q3.w);
        xu_lag = q3.w;
        wprev = w;
        w = wnext;
    }

    // Drain: final A-step (f = 2047). cA = p2 = shfl(mjB(2046)).
    __half2 cB_fin, cA_fin;
    {
        uint32_t mAu = sext(wprev, 30);
        __half2 aA  = u2h2(xu_lag & mAu);
        __half2 cAv = u2h2(p2 & zmask);
        __half2 m1A = __hmul2(sA, aA);
        __half2 g1A = __hfma2(sA, neg2, one);
        __half2 rA  = __hfma2(aA, g1A, sA);
        __half2 mjA = __hfma2(cAv, rA, m1A);
        __half2 g2A = __hfma2(rA, neg2, one);
        sA = __hfma2(cAv, g2A, rA);
        cB_fin = mjA;                        // carry into lane 2sub+1
        cA_fin = u2h2(p1 & zmask);           // shfl(mjB(2047)) from last iter
    }

    // Output float32. Thread sub holds lanes (2sub, 2sub+1) of rows b0, b0+8.
    // s at out[b*4096 + o*8 + lane], c at +65536 floats.
    const int out_i = out_base + (tid >> 2);
    const int baseA = b0 * 4096 + out_i * 8 + 2 * sub;        // row b0
    const int baseB = baseA + 8 * 4096;                       // row b0+8
    float2 sAf = __half22float2(sA), cAf = __half22float2(cA_fin);
    float2 sBf = __half22float2(sB), cBf = __half22float2(cB_fin);
    out[baseA]             = sAf.x;   // row b0,   lane 2sub
    out[baseA + 1]         = sBf.x;   // row b0,   lane 2sub+1
    out[baseB]             = sAf.y;   // row b0+8, lane 2sub
    out[baseB + 1]         = sBf.y;
    out[65536 + baseA]     = cAf.x;
    out[65536 + baseA + 1] = cBf.x;
    out[65536 + baseB]     = cAf.y;
    out[65536 + baseB + 1] = cBf.y;
}

// ---------------------------------------------------------------------------
extern "C" void kernel_launch(void* const* d_in, const int* in_sizes, int n_in,
                              void* d_out, int out_size) {
    const float* x  = (const float*)d_in[0];   // (16, 2048) fp32
    const float* wt = (const float*)d_in[1];   // (2048, 4096) fp32
    float* out = (float*)d_out;                // 131072 fp32: [s | c]

    pack_kernel<<<1024, 256>>>(wt);
    scan_kernel<<<128, 128>>>(x, out);
}